// round 16
// baseline (speedup 1.0000x reference)
#include <cuda_runtime.h>
#include <cstdint>

#define BB 32
#define TT 128
#define DD 512
#define UU 512
#define G4 2048
#define NCTA 128
#define NTHR 1024

typedef unsigned long long ull;

// ---------------- packed fp32x2 helpers (sm_103a FFMA2 path) ---------------
__device__ __forceinline__ ull dup2(float x) {
    ull r; asm("mov.b64 %0, {%1, %1};" : "=l"(r) : "f"(x)); return r;
}
__device__ __forceinline__ void upk2(ull v, float& x, float& y) {
    asm("mov.b64 {%0, %1}, %2;" : "=f"(x), "=f"(y) : "l"(v));
}
__device__ __forceinline__ ull ffma2(ull a, ull b, ull c) {
    ull d; asm("fma.rn.f32x2 %0, %1, %2, %3;" : "=l"(d) : "l"(a), "l"(b), "l"(c));
    return d;
}

// ---------------- scratch (device globals: allocation-free) ----------------
__device__ float g_attx[BB*TT*UU];      // 8 MB   tanh(x@W_att + b_att)
__device__ float g_xk  [BB*TT*G4];      // 32 MB  x@kernel + bias
__device__ float g_hbuf[BB*UU];         // hidden state
__device__ float g_z   [BB*DD];
__device__ float g_scp [BB*4*TT];       // per-(pb,pr) partial scores
__device__ unsigned g_gcnt, g_ggen;          // grid barrier
__device__ unsigned g_lcnt[BB], g_lgen[BB];  // per-batch 4-CTA barriers

__device__ __forceinline__ float my_tanh(float x) {
    x = fminf(fmaxf(x, -15.f), 15.f);
    float e = __expf(2.f * x);
    return __fdividef(e - 1.f, e + 1.f);
}
__device__ __forceinline__ float hsig(float x) {
    return fminf(fmaxf(0.2f * x + 0.5f, 0.f), 1.f);
}

// Software barrier. Safe: all participating CTAs co-resident (1 CTA/SM,
// 128 <= 148 SMs). __threadfence publishes prior writes and invalidates L1.
__device__ __forceinline__ void bar_sync(unsigned* cnt, unsigned* gen, unsigned n) {
    __syncthreads();
    if (threadIdx.x == 0) {
        __threadfence();
        unsigned my = *(volatile unsigned*)gen;
        if (atomicAdd(cnt, 1u) == n - 1u) {
            *cnt = 0u;
            __threadfence();
            atomicAdd(gen, 1u);
        } else {
            while (*(volatile unsigned*)gen == my) { }
        }
        __threadfence();
    }
    __syncthreads();
}

__device__ __forceinline__ void cp_async16(uint32_t dst_smem, const void* src) {
    asm volatile("cp.async.ca.shared.global [%0], [%1], 16;\n"
                 :: "r"(dst_smem), "l"(src));
}

// ---------------- precompute: one SGEMM over virtual N = 2048 + 512 --------
// n<2048 -> g_xk = X@kernel + bias ; n>=2048 -> g_attx = tanh(X@W_att + ab)
__global__ void __launch_bounds__(256) k_pre(
        const float* __restrict__ x, const float* __restrict__ Wk,
        const float* __restrict__ Wa, const float* __restrict__ bias,
        const float* __restrict__ ab) {
    __shared__ float As[16][132];
    __shared__ float Bs[16][64];
    int m0 = blockIdx.y * 128;
    int n0 = blockIdx.x * 64;
    bool isK = (n0 < G4);
    const float* Wm = isK ? Wk : Wa;
    int ldw = isK ? G4 : UU;
    int nc0 = isK ? n0 : (n0 - G4);
    int tid = threadIdx.x;
    int tm = (tid >> 4) * 8;
    int tn = (tid & 15) * 4;
    ull acc2[8][2];
    #pragma unroll
    for (int i = 0; i < 8; i++) { acc2[i][0] = 0ull; acc2[i][1] = 0ull; }

    for (int k0 = 0; k0 < DD; k0 += 16) {
        #pragma unroll
        for (int i = 0; i < 2; i++) {
            int idx = tid + i * 256;
            int row = idx >> 2;
            int c4  = (idx & 3) * 4;
            float4 v = *(const float4*)(x + (size_t)(m0 + row) * DD + k0 + c4);
            As[c4+0][row] = v.x; As[c4+1][row] = v.y;
            As[c4+2][row] = v.z; As[c4+3][row] = v.w;
        }
        {
            int row = tid >> 4;
            int c4  = (tid & 15) * 4;
            *(float4*)&Bs[row][c4] =
                *(const float4*)(Wm + (size_t)(k0 + row) * ldw + nc0 + c4);
        }
        __syncthreads();
        #pragma unroll
        for (int kk = 0; kk < 16; kk++) {
            float4 a0 = *(float4*)&As[kk][tm];
            float4 a1 = *(float4*)&As[kk][tm + 4];
            ulonglong2 bp = *(const ulonglong2*)&Bs[kk][tn];
            float am[8] = {a0.x,a0.y,a0.z,a0.w,a1.x,a1.y,a1.z,a1.w};
            #pragma unroll
            for (int i = 0; i < 8; i++) {
                ull ad = dup2(am[i]);
                acc2[i][0] = ffma2(ad, bp.x, acc2[i][0]);
                acc2[i][1] = ffma2(ad, bp.y, acc2[i][1]);
            }
        }
        __syncthreads();
    }
    const float* bvec = isK ? bias : ab;
    float bj[4];
    #pragma unroll
    for (int j = 0; j < 4; j++) bj[j] = bvec[nc0 + tn + j];
    #pragma unroll
    for (int i = 0; i < 8; i++) {
        int m = m0 + tm + i;
        float c0, c1, c2, c3;
        upk2(acc2[i][0], c0, c1);
        upk2(acc2[i][1], c2, c3);
        float cv[4] = {c0, c1, c2, c3};
        if (isK) {
            float* dst = g_xk + (size_t)m * G4 + nc0 + tn;
            #pragma unroll
            for (int j = 0; j < 4; j++) dst[j] = cv[j] + bj[j];
        } else {
            float* dst = g_attx + (size_t)m * UU + nc0 + tn;
            #pragma unroll
            for (int j = 0; j < 4; j++) dst[j] = my_tanh(cv[j] + bj[j]);
        }
    }
}

// ---------------- persistent scan kernel ------------------------------------
// 128 CTAs x 1024 thr (32 warps), 1 CTA/SM, ~221.7 KB smem. Same phase
// structure as round 14/15, but work split across 2x warps to cover the
// LDS/L2 latency chains (the scan is latency-bound, not issue-bound).
__global__ void __launch_bounds__(NTHR, 1) k_scan(
        const float* __restrict__ x,  const float* __restrict__ R,
        const float* __restrict__ A,  const float* __restrict__ Ua,
        const float* __restrict__ V,  float* __restrict__ out) {
    extern __shared__ float sm[];
    float* W_s    = sm;               // 16384
    float* hz     = sm + 16384;       // 32768 (dedicated)
    float* Asc    = sm + 49152;       // 4608 (A scratch / B reduction)
    float* V_s    = sm + 53760;       // 512
    float* gate_s = sm + 54272;       // 512
    float* c_s    = sm + 54784;       // 128
    float* h_s    = sm + 54912;       // 512
    // total 55424 floats = 221696 B

    float2* pair_s = (float2*)Asc;            // 128 float2 (256 floats)
    float4* hred4  = (float4*)(Asc + 256);    // 4096 floats (A1)
    float4* zred4  = (float4*)(Asc + 256);    // alias (A3, disjoint in time)
    float*  al_s   = Asc + 4352;              // 128
    float*  wr     = Asc + 4480;              // 8
    // Phase-B reduction aliases Asc[0..4096) (after __syncthreads)

    const int bid = blockIdx.x;
    const int tid = threadIdx.x;
    const int u0  = bid * 4;                  // Phase B u-tile
    const int wid = tid >> 5, lane = tid & 31;
    const int pb  = bid >> 2, pr = bid & 3;   // Phase A role
    const uint32_t hz_u32 = (uint32_t)__cvta_generic_to_shared(hz);

    // ---- one-time init ----
    if (tid < 128) {
        g_hbuf[bid * 128 + tid] = 0.f;
        c_s[tid] = 0.f;
    }
    #pragma unroll 4
    for (int i = 0; i < 16; i++) {            // gate weights [R;A]
        int idx = tid + i * 1024;
        int k = idx >> 4, ci = idx & 15;
        int col = ((ci >> 2) << 9) + u0 + (ci & 3);
        W_s[idx] = (k < 512) ? R[(size_t)k * G4 + col]
                             : A[(size_t)(k - 512) * G4 + col];
    }
    if (tid < 512) V_s[tid] = V[tid];
    bar_sync(&g_gcnt, &g_ggen, NCTA);

    for (int t = 0; t < TT; t++) {
        // ========================= Phase A =========================
        // prefetch h_{t-1} -> hz (swizzled) for Phase B
        {
            const float4* h4 = (const float4*)g_hbuf;
            #pragma unroll
            for (int i = 0; i < 4; i++) {
                int idx4 = tid + i * 1024;
                int b  = idx4 >> 7;
                int k0 = (idx4 & 127) << 2;
                uint32_t dst = hz_u32
                    + (b * 1024 + (k0 ^ (((b >> 1) & 7) << 2))) * 4;
                cp_async16(dst, h4 + idx4);
            }
            asm volatile("cp.async.commit_group;\n" ::: "memory");
        }

        // A1: hU slice tanh( h[pb,:] @ Ua[:, pr*128 .. +128) ), kept in smem
        if (tid < 512) h_s[tid] = g_hbuf[pb * UU + tid];
        __syncthreads();
        {
            int c4 = tid & 31;            // float4 col in 128-col slice
            int ks = tid >> 5;            // 0..31, 16 k each
            const ulonglong2* up = (const ulonglong2*)Ua
                               + (size_t)(ks * 16) * 128 + pr * 32 + c4;
            ull a01 = 0ull, a23 = 0ull;
            #pragma unroll 8
            for (int j = 0; j < 16; j++) {
                ull hd = dup2(h_s[ks * 16 + j]);
                ulonglong2 w = up[(size_t)j * 128];
                a01 = ffma2(hd, w.x, a01);
                a23 = ffma2(hd, w.y, a23);
            }
            float4 a;
            upk2(a01, a.x, a.y);
            upk2(a23, a.z, a.w);
            hred4[ks * 32 + c4] = a;
        }
        __syncthreads();
        if (tid < 32) {
            float4 s = hred4[tid];
            #pragma unroll
            for (int k = 1; k < 32; k++) {
                float4 v = hred4[k * 32 + tid];
                s.x += v.x; s.y += v.y; s.z += v.z; s.w += v.w;
            }
            int ub = pr * 128 + tid * 4;
            pair_s[tid*4+0] = make_float2(my_tanh(s.x), V_s[ub+0]);
            pair_s[tid*4+1] = make_float2(my_tanh(s.y), V_s[ub+1]);
            pair_s[tid*4+2] = make_float2(my_tanh(s.z), V_s[ub+2]);
            pair_s[tid*4+3] = make_float2(my_tanh(s.w), V_s[ub+3]);
        }
        __syncthreads();

        // A2: partial scores over OWN u-slice, 32 warps x 4 timesteps
        {
            float2 q0 = pair_s[lane*4+0], q1 = pair_s[lane*4+1];
            float2 q2 = pair_s[lane*4+2], q3 = pair_s[lane*4+3];
            const float4* ax = (const float4*)g_attx;
            float p[4];
            #pragma unroll
            for (int i = 0; i < 4; i++) p[i] = 0.f;
            #pragma unroll
            for (int tt = 0; tt < 4; tt++) {
                int tp = wid + tt * 32;
                float4 av = ax[((size_t)(pb * TT + tp)) * 128 + pr * 32 + lane];
                p[tt] = fmaf(__fdividef(av.x + q0.x, fmaf(av.x, q0.x, 1.f)), q0.y, p[tt]);
                p[tt] = fmaf(__fdividef(av.y + q1.x, fmaf(av.y, q1.x, 1.f)), q1.y, p[tt]);
                p[tt] = fmaf(__fdividef(av.z + q2.x, fmaf(av.z, q2.x, 1.f)), q2.y, p[tt]);
                p[tt] = fmaf(__fdividef(av.w + q3.x, fmaf(av.w, q3.x, 1.f)), q3.y, p[tt]);
            }
            #pragma unroll
            for (int tt = 0; tt < 4; tt++) {
                #pragma unroll
                for (int off = 16; off; off >>= 1)
                    p[tt] += __shfl_xor_sync(0xffffffffu, p[tt], off);
            }
            if (lane == 0) {
                #pragma unroll
                for (int tt = 0; tt < 4; tt++)
                    g_scp[(pb * 4 + pr) * TT + wid + tt * 32] = p[tt];
            }
        }
        bar_sync(&g_lcnt[pb], &g_lgen[pb], 4u);

        // A3: combine partials + softmax over T (redundant x4) + z slice
        {
            float sv = -1e30f;
            if (tid < 128) {
                sv = g_scp[(pb * 4 + 0) * TT + tid]
                   + g_scp[(pb * 4 + 1) * TT + tid]
                   + g_scp[(pb * 4 + 2) * TT + tid]
                   + g_scp[(pb * 4 + 3) * TT + tid];
            }
            float mv = sv;
            #pragma unroll
            for (int off = 16; off; off >>= 1)
                mv = fmaxf(mv, __shfl_xor_sync(0xffffffffu, mv, off));
            if (lane == 0 && wid < 4) wr[wid] = mv;
            __syncthreads();
            float mx = fmaxf(fmaxf(wr[0], wr[1]), fmaxf(wr[2], wr[3]));
            float e = (tid < 128) ? __expf(sv - mx) : 0.f;
            float es = e;
            #pragma unroll
            for (int off = 16; off; off >>= 1)
                es += __shfl_xor_sync(0xffffffffu, es, off);
            if (lane == 0 && wid < 4) wr[4 + wid] = es;
            __syncthreads();
            float tot = wr[4] + wr[5] + wr[6] + wr[7];
            if (tid < 128) al_s[tid] = e * __fdividef(1.f, tot);
            __syncthreads();

            int c4 = tid & 31;            // float4 d-col in 128-d slice
            int tg = tid >> 5;            // 0..31 -> 4 timesteps each
            const ulonglong2* x2 = (const ulonglong2*)(x + (size_t)pb * TT * DD + pr * 128);
            ull z01 = 0ull, z23 = 0ull;
            #pragma unroll
            for (int j = 0; j < 4; j++) {
                int ts = tg * 4 + j;
                ull ad = dup2(al_s[ts]);
                ulonglong2 xv = x2[(size_t)ts * 128 + c4];
                z01 = ffma2(ad, xv.x, z01);
                z23 = ffma2(ad, xv.y, z23);
            }
            float4 zp;
            upk2(z01, zp.x, zp.y);
            upk2(z23, zp.z, zp.w);
            zred4[tg * 32 + c4] = zp;
            __syncthreads();
            if (tid < 32) {
                float4 s = zred4[tid];
                #pragma unroll
                for (int k = 1; k < 32; k++) {
                    float4 v = zred4[k * 32 + tid];
                    s.x += v.x; s.y += v.y; s.z += v.z; s.w += v.w;
                }
                ((float4*)(g_z + pb * DD + pr * 128))[tid] = s;
            }
        }
        bar_sync(&g_gcnt, &g_ggen, NCTA);

        // ========================= Phase B =========================
        {
            float xkv = 0.f;
            if (tid < 512) {
                int b = tid >> 4, ci = tid & 15;
                int col = ((ci >> 2) << 9) + u0 + (ci & 3);
                xkv = g_xk[((size_t)(b * TT) + t) * G4 + col];
            }
            // stage z (h already arriving via cp.async)
            const float4* z4 = (const float4*)g_z;
            #pragma unroll
            for (int i = 0; i < 4; i++) {
                int idx4 = tid + i * 1024;
                int b  = idx4 >> 7;
                int k0 = ((idx4 & 127) << 2) + 512;
                float4 v = z4[idx4];
                *(float4*)&hz[b * 1024 + (k0 ^ (((b >> 1) & 7) << 2))] = v;
            }
            asm volatile("cp.async.wait_group 0;\n" ::: "memory");
            __syncthreads();

            // 1024 thr = 8 k-slices x 16 b-pairs x 8 col-pairs
            int ks = tid >> 7;            // 0..7 (warp-uniform)
            int bq = (tid >> 3) & 15;     // b pair
            int cp = tid & 7;             // col pair (2 gate cols)
            int b0 = bq * 2, b1 = b0 + 1;
            int m0 = (bq & 7) << 2;       // = ((b0>>1)&7)<<2 = ((b1>>1)&7)<<2
            const float* hp0 = &hz[b0 * 1024];
            const float* hp1 = &hz[b1 * 1024];
            const float* wp  = &W_s[cp * 2];
            ull A0 = 0ull, A1 = 0ull;
            int kb = ks * 128;
            #pragma unroll 8
            for (int k2 = 0; k2 < 64; k2++) {
                int k = kb + k2 * 2;
                float2 hv0 = *(const float2*)&hp0[k ^ m0];
                float2 hv1 = *(const float2*)&hp1[k ^ m0];
                ull w0 = *(const ull*)&wp[k * 16];
                ull w1 = *(const ull*)&wp[(k + 1) * 16];
                A0 = ffma2(dup2(hv0.x), w0, A0);
                A1 = ffma2(dup2(hv1.x), w0, A1);
                A0 = ffma2(dup2(hv0.y), w1, A0);
                A1 = ffma2(dup2(hv1.y), w1, A1);
            }
            __syncthreads();
            float* red = Asc;             // 8 x 512 partials
            *(ull*)&red[ks * 512 + b0 * 16 + cp * 2] = A0;
            *(ull*)&red[ks * 512 + b1 * 16 + cp * 2] = A1;
            __syncthreads();
            if (tid < 512) {
                float g = xkv;
                #pragma unroll
                for (int s2 = 0; s2 < 8; s2++) g += red[s2 * 512 + tid];
                gate_s[tid] = g;
            }
            __syncthreads();
            if (tid < 128) {
                int b = tid >> 2, jj = tid & 3;
                float gi = hsig(gate_s[b * 16 + 0  + jj]);
                float gf = hsig(gate_s[b * 16 + 4  + jj]);
                float gg = my_tanh(gate_s[b * 16 + 8  + jj]);
                float go = hsig(gate_s[b * 16 + 12 + jj]);
                float cn = gf * c_s[tid] + gi * gg;
                c_s[tid] = cn;
                float hn = go * my_tanh(cn);
                int idx = b * UU + u0 + jj;
                g_hbuf[idx] = hn;
                out[((size_t)b * TT + t) * UU + u0 + jj] = hn;
            }
        }
        bar_sync(&g_gcnt, &g_ggen, NCTA);
    }
}

// ---------------------------------------------------------------------------
extern "C" void kernel_launch(void* const* d_in, const int* in_sizes, int n_in,
                              void* d_out, int out_size) {
    const float* x    = (const float*)d_in[0];
    const float* Wk   = (const float*)d_in[1];  // kernel (D,4U)
    const float* R    = (const float*)d_in[2];  // recurrent_kernel (U,4U)
    const float* A    = (const float*)d_in[3];  // attention_kernel (D,4U)
    const float* Wa   = (const float*)d_in[4];  // attention_W (D,U)
    const float* Ua   = (const float*)d_in[5];  // attention_U (U,U)
    const float* V    = (const float*)d_in[6];  // attention_V (U,1)
    const float* bias = (const float*)d_in[7];  // (4U)
    const float* ab   = (const float*)d_in[8];  // attention_b (U)
    float* out = (float*)d_out;

    const int SCAN_SMEM = 55424 * 4;  // 221696 B
    cudaFuncSetAttribute(k_scan, cudaFuncAttributeMaxDynamicSharedMemorySize,
                         SCAN_SMEM);

    k_pre<<<dim3(40, 32), 256>>>(x, Wk, Wa, bias, ab);
    k_scan<<<NCTA, NTHR, SCAN_SMEM>>>(x, R, A, Ua, V, out);
}